// round 15
// baseline (speedup 1.0000x reference)
#include <cuda_runtime.h>
#include <cuda_fp16.h>
#include <cstdint>
#include <math.h>

// Problem constants
#define NT 1024
#define NA 2
#define NE 8
#define NI 2816
#define ND 1024
#define NSLOT (NT * NA)

// GEMM tiling: block 128x128x64, 512 threads (16 warps: 4M x 4N), 3-stage pipe
#define BM 128
#define BN 128
#define BK 64
#define LDS_STRIDE 144             // bytes per smem tile row (64*2 padded to 144)
#define TB (128 * LDS_STRIDE)      // one tile: 128 rows x 144B = 18432 B

// ---------------------------------------------------------------------------
// Device global scratch
// ---------------------------------------------------------------------------
__device__ int g_count[NE];
__device__ int g_slots[NE][NSLOT];
__device__ int g_is64;

__device__ __align__(16) __half g_x16[NT * ND];
__device__ __align__(16) __half g_h16[(size_t)NSLOT * NI];

// ---------------------------------------------------------------------------
// PTX helpers (base-target sm_103 features only)
// ---------------------------------------------------------------------------
__device__ __forceinline__ uint32_t smem_u32(const void* p) {
    uint32_t a;
    asm("{ .reg .u64 t; cvta.to.shared.u64 t, %1; cvt.u32.u64 %0, t; }"
        : "=r"(a) : "l"(p));
    return a;
}

#define LDSM4(R, addr) \
    asm volatile("ldmatrix.sync.aligned.m8n8.x4.shared.b16 {%0,%1,%2,%3}, [%4];" \
        : "=r"((R)[0]), "=r"((R)[1]), "=r"((R)[2]), "=r"((R)[3]) : "r"(addr))

#define MMA_F16(C, A, B0, B1) \
    asm volatile("mma.sync.aligned.m16n8k16.row.col.f32.f16.f16.f32 " \
        "{%0,%1,%2,%3}, {%4,%5,%6,%7}, {%8,%9}, {%0,%1,%2,%3};" \
        : "+f"((C)[0]), "+f"((C)[1]), "+f"((C)[2]), "+f"((C)[3]) \
        : "r"((A)[0]), "r"((A)[1]), "r"((A)[2]), "r"((A)[3]), "r"(B0), "r"(B1))

#define CP_ASYNC16(dst, src) \
    asm volatile("cp.async.cg.shared.global [%0], [%1], 16;" :: "r"(dst), "l"(src))
#define CP_COMMIT() asm volatile("cp.async.commit_group;" ::: "memory")
#define CP_WAIT(N) asm volatile("cp.async.wait_group %0;" :: "n"(N) : "memory")

__device__ __forceinline__ uint32_t pack2h(float a, float b) {
    __half2 h = __floats2half2_rn(a, b);
    return *reinterpret_cast<uint32_t*>(&h);
}
// 8 fp32 -> 8 packed fp16 (uint4)
__device__ __forceinline__ uint4 pack8h(const float4& a, const float4& b) {
    uint4 r;
    r.x = pack2h(a.x, a.y);
    r.y = pack2h(a.z, a.w);
    r.z = pack2h(b.x, b.y);
    r.w = pack2h(b.z, b.w);
    return r;
}

// ---------------------------------------------------------------------------
// Routing
// ---------------------------------------------------------------------------
__global__ void detect_and_zero_kernel(const int* __restrict__ idx32) {
    __shared__ int any;
    if (threadIdx.x == 0) any = 0;
    if (threadIdx.x < NE) g_count[threadIdx.x] = 0;
    __syncthreads();
    int local = 0;
    for (int i = threadIdx.x; i < NSLOT / 2; i += blockDim.x)
        local |= idx32[2 * i + 1];
    if (local) atomicOr(&any, 1);
    __syncthreads();
    if (threadIdx.x == 0) g_is64 = (any == 0) ? 1 : 0;
}

__global__ void route_kernel(const int* __restrict__ idx32) {
    int s = blockIdx.x * blockDim.x + threadIdx.x;
    if (s < NSLOT) {
        int e = g_is64 ? idx32[2 * s] : idx32[s];
        e &= (NE - 1);
        int p = atomicAdd(&g_count[e], 1);
        g_slots[e][p] = s;
    }
}

// ---------------------------------------------------------------------------
// x: fp32 -> fp16 (tiny)
// ---------------------------------------------------------------------------
__global__ __launch_bounds__(256) void conv_f16_kernel(
    const float* __restrict__ src, __half* __restrict__ dst, int n8)
{
    int i = blockIdx.x * blockDim.x + threadIdx.x;
    if (i >= n8) return;
    float4 a = reinterpret_cast<const float4*>(src)[2 * i];
    float4 b = reinterpret_cast<const float4*>(src)[2 * i + 1];
    reinterpret_cast<uint4*>(dst)[i] = pack8h(a, b);
}

// ---------------------------------------------------------------------------
// GEMM1: h = silu(X @ w1[e]^T) * (X @ w3[e]^T). Pure fp16, fp32 acc.
// BK=64, 3-stage pipeline, ONE barrier per chunk (R11 skeleton, 4 kb blocks):
//   CP_WAIT(1) -> sync -> cp.async(c+2) -> Wldg b0 -> kb0,kb1 MMA ->
//   Wsts b0 -> Wldg b1 -> kb2,kb3 MMA -> Wsts b1
// Stage tiles: A, B1, B3 (each 128 x 64 fp16, 144B stride)
// ---------------------------------------------------------------------------
#define STAGE1B (3 * TB)                    // 55296
#define SMEM1_BYTES (1024 + 3 * STAGE1B)    // 166912

__global__ __launch_bounds__(512, 1) void gemm1_tc(
    const float* __restrict__ w1, const float* __restrict__ w3)
{
    const int e = blockIdx.z;
    const int ne = g_count[e];
    const int mBase = blockIdx.y * BM;
    if (mBase >= ne) return;
    const int nBase = blockIdx.x * BN;

    extern __shared__ char smem[];
    const uint32_t sb = smem_u32(smem);
    const int tid = threadIdx.x;
    const int wid = tid >> 5;
    const int lane = tid & 31;

    int* sSlot = reinterpret_cast<int*>(smem);
    if (tid < BM) {
        int m = mBase + tid;
        sSlot[tid] = (m < ne) ? g_slots[e][m] : -1;
    }
    __syncthreads();

    // --- A producer: two 16B granules per thread (rows r and r+64) ---
    const int arow = tid >> 3;           // 0..63
    const int acol = tid & 7;            // x16B within the 128B row
    const uint32_t adoff0 = 1024u + (uint32_t)arow * LDS_STRIDE + acol * 16;
    const uint32_t adoff1 = adoff0 + 64u * LDS_STRIDE;
    const __half *asrc0, *asrc1;
    {
        int s0 = sSlot[arow];
        int s1 = sSlot[arow + 64];
        asrc0 = g_x16 + (size_t)((s0 >= 0 ? s0 : 0) >> 1) * ND + acol * 8;
        asrc1 = g_x16 + (size_t)((s1 >= 0 ? s1 : 0) >> 1) * ND + acol * 8;
    }

    // --- W producer: 32 fp32 per thread per chunk in 2 batches of 16 ---
    const int wt    = tid >> 8;            // 0: w1, 1: w3
    const int wrow  = (tid & 255) >> 1;    // 0..127
    const int whalf = tid & 1;             // fp32 cols [whalf*32, +32)
    const float* wsrc = (wt == 0 ? w1 : w3)
        + (size_t)e * NI * ND + (size_t)(nBase + wrow) * ND + whalf * 32;
    const uint32_t wdoff = (uint32_t)wrow * LDS_STRIDE + whalf * 64;
    const uint32_t wtoff = (uint32_t)(1 + wt) * TB;   // B1 or B3 within stage

    // --- consumer: 16 warps = 4M x 4N, warp tile 32x32 ---
    const int warpM = wid & 3;
    const int warpN = wid >> 2;
    const uint32_t aoff = (uint32_t)(warpM * 32 + (lane & 15)) * LDS_STRIDE
                        + (uint32_t)(lane >> 4) * 16;
    const uint32_t boff = (uint32_t)(warpN * 32 + (lane & 7) + ((lane >> 3) & 2) * 4) * LDS_STRIDE
                        + (uint32_t)((lane >> 3) & 1) * 16;

    float acc1[2][4][4] = {};
    float acc3[2][4][4] = {};

    const int NCH = ND / BK;   // 16

    auto wsts = [&](uint32_t stg, int b, const float4& s0, const float4& s1,
                    const float4& s2, const float4& s3) {
        *reinterpret_cast<uint4*>(smem + 1024u + stg + wtoff + wdoff + b * 32)
            = pack8h(s0, s1);
        *reinterpret_cast<uint4*>(smem + 1024u + stg + wtoff + wdoff + b * 32 + 16)
            = pack8h(s2, s3);
    };

    // --- prologue: cp A for chunks 0,1 (stages 0,1); W chunk 0 both batches ---
    CP_ASYNC16(adoff0 + sb, asrc0);
    CP_ASYNC16(adoff1 + sb, asrc1);
    CP_COMMIT();
    CP_ASYNC16(adoff0 + sb + STAGE1B, asrc0 + BK);
    CP_ASYNC16(adoff1 + sb + STAGE1B, asrc1 + BK);
    CP_COMMIT();
    {
        float4 s0 = *reinterpret_cast<const float4*>(wsrc + 0);
        float4 s1 = *reinterpret_cast<const float4*>(wsrc + 4);
        float4 s2 = *reinterpret_cast<const float4*>(wsrc + 8);
        float4 s3 = *reinterpret_cast<const float4*>(wsrc + 12);
        wsts(0, 0, s0, s1, s2, s3);
        s0 = *reinterpret_cast<const float4*>(wsrc + 16);
        s1 = *reinterpret_cast<const float4*>(wsrc + 20);
        s2 = *reinterpret_cast<const float4*>(wsrc + 24);
        s3 = *reinterpret_cast<const float4*>(wsrc + 28);
        wsts(0, 1, s0, s1, s2, s3);
    }

    uint32_t stgRd = 0, stgW = STAGE1B, stgCp = 2 * STAGE1B;

    for (int c = 0; c < NCH; c++) {
        const bool haveCp = (c + 2 < NCH);
        const bool haveW  = (c + 1 < NCH);
        const int kt = (c + 1) * BK;

        if (c + 1 < NCH) { CP_WAIT(1); } else { CP_WAIT(0); }
        __syncthreads();
        if (haveCp) {
            const int kt2 = (c + 2) * BK;
            CP_ASYNC16(adoff0 + sb + stgCp, asrc0 + kt2);
            CP_ASYNC16(adoff1 + sb + stgCp, asrc1 + kt2);
            CP_COMMIT();
        }

        const uint32_t bb = sb + 1024u + stgRd;
        const uint32_t tA = bb;
        const uint32_t tB1 = bb + TB, tB3 = bb + 2 * TB;

        auto do_kb = [&](uint32_t ko) {
            uint32_t a[2][4];
            #pragma unroll
            for (int mb = 0; mb < 2; mb++)
                LDSM4(a[mb], tA + aoff + mb * (16 * LDS_STRIDE) + ko);
            #pragma unroll
            for (int nb2 = 0; nb2 < 2; nb2++) {
                const uint32_t no = nb2 * (16 * LDS_STRIDE);
                const int j0 = 2 * nb2, j1 = 2 * nb2 + 1;
                uint32_t b1[4], b3[4];
                LDSM4(b1, tB1 + boff + no + ko);
                LDSM4(b3, tB3 + boff + no + ko);
                MMA_F16(acc1[0][j0], a[0], b1[0], b1[1]);
                MMA_F16(acc1[0][j1], a[0], b1[2], b1[3]);
                MMA_F16(acc1[1][j0], a[1], b1[0], b1[1]);
                MMA_F16(acc1[1][j1], a[1], b1[2], b1[3]);
                MMA_F16(acc3[0][j0], a[0], b3[0], b3[1]);
                MMA_F16(acc3[0][j1], a[0], b3[2], b3[3]);
                MMA_F16(acc3[1][j0], a[1], b3[0], b3[1]);
                MMA_F16(acc3[1][j1], a[1], b3[2], b3[3]);
            }
        };

        // W batch0 LDG -> kb0,kb1 -> batch0 STS -> batch1 LDG -> kb2,kb3 -> STS
        float4 s0, s1, s2, s3;
        if (haveW) {
            s0 = *reinterpret_cast<const float4*>(wsrc + kt + 0);
            s1 = *reinterpret_cast<const float4*>(wsrc + kt + 4);
            s2 = *reinterpret_cast<const float4*>(wsrc + kt + 8);
            s3 = *reinterpret_cast<const float4*>(wsrc + kt + 12);
        }
        do_kb(0);
        do_kb(32);
        if (haveW) {
            wsts(stgW, 0, s0, s1, s2, s3);
            s0 = *reinterpret_cast<const float4*>(wsrc + kt + 16);
            s1 = *reinterpret_cast<const float4*>(wsrc + kt + 20);
            s2 = *reinterpret_cast<const float4*>(wsrc + kt + 24);
            s3 = *reinterpret_cast<const float4*>(wsrc + kt + 28);
        }
        do_kb(64);
        do_kb(96);
        if (haveW) wsts(stgW, 1, s0, s1, s2, s3);

        const uint32_t t = stgRd;
        stgRd = stgW; stgW = stgCp; stgCp = t;
    }

    // --- epilogue: SwiGLU, store h as fp16 ---
    const int g = lane >> 2;
    const int tg = lane & 3;
    #pragma unroll
    for (int mb = 0; mb < 2; mb++) {
        #pragma unroll
        for (int half = 0; half < 2; half++) {
            const int r = warpM * 32 + mb * 16 + g + half * 8;
            const int s = sSlot[r];
            if (s < 0) continue;
            #pragma unroll
            for (int nb = 0; nb < 4; nb++) {
                const float v1a = acc1[mb][nb][half * 2];
                const float v1b = acc1[mb][nb][half * 2 + 1];
                const float v3a = acc3[mb][nb][half * 2];
                const float v3b = acc3[mb][nb][half * 2 + 1];
                const float ha = v1a / (1.0f + __expf(-v1a)) * v3a;
                const float hb = v1b / (1.0f + __expf(-v1b)) * v3b;
                const size_t o = (size_t)s * NI + (nBase + warpN * 32 + nb * 8 + tg * 2);
                *reinterpret_cast<uint32_t*>(g_h16 + o) = pack2h(ha, hb);
            }
        }
    }
}

// ---------------------------------------------------------------------------
// GEMM2: out[slot,:] = h[slot,:] @ w2[e]^T. Pure fp16, BK=64.
// Same 3-stage / 1-barrier scheme, 4 kb blocks, single 16-float W batch.
// Stage tiles: A, B (each 128 x 64 fp16, 144B stride)
// ---------------------------------------------------------------------------
#define STAGE2B (2 * TB)                    // 36864
#define SMEM2_BYTES (1024 + 3 * STAGE2B)    // 111616

__global__ __launch_bounds__(512, 1) void gemm2_tc(
    const float* __restrict__ w2, float* __restrict__ out)
{
    const int e = blockIdx.z;
    const int ne = g_count[e];
    const int mBase = blockIdx.y * BM;
    if (mBase >= ne) return;
    const int nBase = blockIdx.x * BN;

    extern __shared__ char smem[];
    const uint32_t sb = smem_u32(smem);
    const int tid = threadIdx.x;
    const int wid = tid >> 5;
    const int lane = tid & 31;

    int* sSlot = reinterpret_cast<int*>(smem);
    if (tid < BM) {
        int m = mBase + tid;
        sSlot[tid] = (m < ne) ? g_slots[e][m] : -1;
    }
    __syncthreads();

    // --- A producer: two 16B granules per thread ---
    const int arow = tid >> 3;
    const int acol = tid & 7;
    const uint32_t adoff0 = 1024u + (uint32_t)arow * LDS_STRIDE + acol * 16;
    const uint32_t adoff1 = adoff0 + 64u * LDS_STRIDE;
    const __half *asrc0, *asrc1;
    {
        int s0 = sSlot[arow];
        int s1 = sSlot[arow + 64];
        asrc0 = g_h16 + (size_t)(s0 >= 0 ? s0 : 0) * NI + acol * 8;
        asrc1 = g_h16 + (size_t)(s1 >= 0 ? s1 : 0) * NI + acol * 8;
    }

    // --- W producer: 16 fp32 per thread per chunk ---
    const int wrow = tid >> 2;           // 0..127
    const int wq   = tid & 3;            // fp32 cols [wq*16, +16)
    const float* wsrc = w2 + (size_t)e * ND * NI + (size_t)(nBase + wrow) * NI + wq * 16;
    const uint32_t wdoff = (uint32_t)wrow * LDS_STRIDE + wq * 32;
    const uint32_t wtoff = TB;

    const int warpM = wid & 3;
    const int warpN = wid >> 2;
    const uint32_t aoff = (uint32_t)(warpM * 32 + (lane & 15)) * LDS_STRIDE
                        + (uint32_t)(lane >> 4) * 16;
    const uint32_t boff = (uint32_t)(warpN * 32 + (lane & 7) + ((lane >> 3) & 2) * 4) * LDS_STRIDE
                        + (uint32_t)((lane >> 3) & 1) * 16;

    float acc[2][4][4] = {};

    const int NCH = NI / BK;   // 44

    auto wsts = [&](uint32_t stg, const float4& s0, const float4& s1,
                    const float4& s2, const float4& s3) {
        *reinterpret_cast<uint4*>(smem + 1024u + stg + wtoff + wdoff)      = pack8h(s0, s1);
        *reinterpret_cast<uint4*>(smem + 1024u + stg + wtoff + wdoff + 16) = pack8h(s2, s3);
    };

    // --- prologue ---
    CP_ASYNC16(adoff0 + sb, asrc0);
    CP_ASYNC16(adoff1 + sb, asrc1);
    CP_COMMIT();
    CP_ASYNC16(adoff0 + sb + STAGE2B, asrc0 + BK);
    CP_ASYNC16(adoff1 + sb + STAGE2B, asrc1 + BK);
    CP_COMMIT();
    {
        float4 s0 = *reinterpret_cast<const float4*>(wsrc + 0);
        float4 s1 = *reinterpret_cast<const float4*>(wsrc + 4);
        float4 s2 = *reinterpret_cast<const float4*>(wsrc + 8);
        float4 s3 = *reinterpret_cast<const float4*>(wsrc + 12);
        wsts(0, s0, s1, s2, s3);
    }

    uint32_t stgRd = 0, stgW = STAGE2B, stgCp = 2 * STAGE2B;

    for (int c = 0; c < NCH; c++) {
        const bool haveCp = (c + 2 < NCH);
        const bool haveW  = (c + 1 < NCH);
        const int kt = (c + 1) * BK;

        if (c + 1 < NCH) { CP_WAIT(1); } else { CP_WAIT(0); }
        __syncthreads();
        if (haveCp) {
            const int kt2 = (c + 2) * BK;
            CP_ASYNC16(adoff0 + sb + stgCp, asrc0 + kt2);
            CP_ASYNC16(adoff1 + sb + stgCp, asrc1 + kt2);
            CP_COMMIT();
        }
        float4 s0, s1, s2, s3;
        if (haveW) {
            s0 = *reinterpret_cast<const float4*>(wsrc + kt + 0);
            s1 = *reinterpret_cast<const float4*>(wsrc + kt + 4);
            s2 = *reinterpret_cast<const float4*>(wsrc + kt + 8);
            s3 = *reinterpret_cast<const float4*>(wsrc + kt + 12);
        }

        const uint32_t bb = sb + 1024u + stgRd;
        const uint32_t tA = bb;
        const uint32_t tBh = bb + TB;

        auto do_kb = [&](uint32_t ko) {
            uint32_t a[2][4];
            #pragma unroll
            for (int mb = 0; mb < 2; mb++)
                LDSM4(a[mb], tA + aoff + mb * (16 * LDS_STRIDE) + ko);
            uint32_t bh0[4], bh1[4];
            LDSM4(bh0, tBh + boff + ko);
            LDSM4(bh1, tBh + boff + 16 * LDS_STRIDE + ko);
            MMA_F16(acc[0][0], a[0], bh0[0], bh0[1]);
            MMA_F16(acc[0][1], a[0], bh0[2], bh0[3]);
            MMA_F16(acc[1][0], a[1], bh0[0], bh0[1]);
            MMA_F16(acc[1][1], a[1], bh0[2], bh0[3]);
            MMA_F16(acc[0][2], a[0], bh1[0], bh1[1]);
            MMA_F16(acc[0][3], a[0], bh1[2], bh1[3]);
            MMA_F16(acc[1][2], a[1], bh1[0], bh1[1]);
            MMA_F16(acc[1][3], a[1], bh1[2], bh1[3]);
        };

        do_kb(0);
        do_kb(32);
        if (haveW) wsts(stgW, s0, s1, s2, s3);
        do_kb(64);
        do_kb(96);

        const uint32_t t = stgRd;
        stgRd = stgW; stgW = stgCp; stgCp = t;
    }

    // --- epilogue: fp32 direct stores ---
    const int g = lane >> 2;
    const int tg = lane & 3;
    #pragma unroll
    for (int mb = 0; mb < 2; mb++) {
        #pragma unroll
        for (int half = 0; half < 2; half++) {
            const int r = warpM * 32 + mb * 16 + g + half * 8;
            const int s = sSlot[r];
            if (s < 0) continue;
            #pragma unroll
            for (int nb = 0; nb < 4; nb++) {
                float2 v;
                v.x = acc[mb][nb][half * 2];
                v.y = acc[mb][nb][half * 2 + 1];
                const size_t o = (size_t)s * ND + (nBase + warpN * 32 + nb * 8 + tg * 2);
                *reinterpret_cast<float2*>(out + o) = v;
            }
        }
    }
}

// ---------------------------------------------------------------------------
// Launch. Inputs (metadata order): x, w1, w2, w3, expert_indices.
// ---------------------------------------------------------------------------
extern "C" void kernel_launch(void* const* d_in, const int* in_sizes, int n_in,
                              void* d_out, int out_size) {
    const float* x  = (const float*)d_in[0];
    const float* w1 = (const float*)d_in[1];
    const float* w2 = (const float*)d_in[2];
    const float* w3 = (const float*)d_in[3];
    const int*   idx = (const int*)d_in[4];
    float* out = (float*)d_out;

    cudaFuncSetAttribute(gemm1_tc, cudaFuncAttributeMaxDynamicSharedMemorySize, SMEM1_BYTES);
    cudaFuncSetAttribute(gemm2_tc, cudaFuncAttributeMaxDynamicSharedMemorySize, SMEM2_BYTES);

    __half* x16;
    cudaGetSymbolAddress((void**)&x16, g_x16);

    detect_and_zero_kernel<<<1, 256>>>(idx);
    route_kernel<<<NSLOT / 256, 256>>>(idx);

    const int nX8 = NT * ND / 8;
    conv_f16_kernel<<<nX8 / 256, 256>>>(x, x16, nX8);

    gemm1_tc<<<dim3(NI / BN, NSLOT / BM, NE), 512, SMEM1_BYTES>>>(w1, w3);
    gemm2_tc<<<dim3(ND / BN, NSLOT / BM, NE), 512, SMEM2_BYTES>>>(w2, out);
}

// round 16
// speedup vs baseline: 1.0319x; 1.0319x over previous
#include <cuda_runtime.h>
#include <cuda_fp16.h>
#include <cstdint>
#include <math.h>

// Problem constants
#define NT 1024
#define NA 2
#define NE 8
#define NI 2816
#define ND 1024
#define NSLOT (NT * NA)

// gemm1: block 128x128x32, 512 thr (16 warps 4Mx4N, warp 32x32)  [R11 exact]
// gemm2: block 128x256x32, 512 thr (16 warps 4Mx4N, warp 32x64)
#define BM 128
#define BN 128
#define BN2 256
#define BK 32
#define LDS_STRIDE 80              // bytes per smem tile row (32*2 padded to 80)
#define TB (128 * LDS_STRIDE)      // 128-row tile: 10240 B
#define TB2 (256 * LDS_STRIDE)     // 256-row tile: 20480 B

// ---------------------------------------------------------------------------
// Device global scratch
// ---------------------------------------------------------------------------
__device__ int g_count[NE];
__device__ int g_slots[NE][NSLOT];
__device__ int g_is64;

__device__ __align__(16) __half g_x16[NT * ND];
__device__ __align__(16) __half g_h16[(size_t)NSLOT * NI];

// ---------------------------------------------------------------------------
// PTX helpers (base-target sm_103 features only)
// ---------------------------------------------------------------------------
__device__ __forceinline__ uint32_t smem_u32(const void* p) {
    uint32_t a;
    asm("{ .reg .u64 t; cvta.to.shared.u64 t, %1; cvt.u32.u64 %0, t; }"
        : "=r"(a) : "l"(p));
    return a;
}

#define LDSM4(R, addr) \
    asm volatile("ldmatrix.sync.aligned.m8n8.x4.shared.b16 {%0,%1,%2,%3}, [%4];" \
        : "=r"((R)[0]), "=r"((R)[1]), "=r"((R)[2]), "=r"((R)[3]) : "r"(addr))

#define MMA_F16(C, A, B0, B1) \
    asm volatile("mma.sync.aligned.m16n8k16.row.col.f32.f16.f16.f32 " \
        "{%0,%1,%2,%3}, {%4,%5,%6,%7}, {%8,%9}, {%0,%1,%2,%3};" \
        : "+f"((C)[0]), "+f"((C)[1]), "+f"((C)[2]), "+f"((C)[3]) \
        : "r"((A)[0]), "r"((A)[1]), "r"((A)[2]), "r"((A)[3]), "r"(B0), "r"(B1))

#define CP_ASYNC16(dst, src) \
    asm volatile("cp.async.cg.shared.global [%0], [%1], 16;" :: "r"(dst), "l"(src))
#define CP_COMMIT() asm volatile("cp.async.commit_group;" ::: "memory")
#define CP_WAIT(N) asm volatile("cp.async.wait_group %0;" :: "n"(N) : "memory")

__device__ __forceinline__ uint32_t pack2h(float a, float b) {
    __half2 h = __floats2half2_rn(a, b);
    return *reinterpret_cast<uint32_t*>(&h);
}
// 8 fp32 -> 8 packed fp16 (uint4)
__device__ __forceinline__ uint4 pack8h(const float4& a, const float4& b) {
    uint4 r;
    r.x = pack2h(a.x, a.y);
    r.y = pack2h(a.z, a.w);
    r.z = pack2h(b.x, b.y);
    r.w = pack2h(b.z, b.w);
    return r;
}

// ---------------------------------------------------------------------------
// Routing
// ---------------------------------------------------------------------------
__global__ void detect_and_zero_kernel(const int* __restrict__ idx32) {
    __shared__ int any;
    if (threadIdx.x == 0) any = 0;
    if (threadIdx.x < NE) g_count[threadIdx.x] = 0;
    __syncthreads();
    int local = 0;
    for (int i = threadIdx.x; i < NSLOT / 2; i += blockDim.x)
        local |= idx32[2 * i + 1];
    if (local) atomicOr(&any, 1);
    __syncthreads();
    if (threadIdx.x == 0) g_is64 = (any == 0) ? 1 : 0;
}

__global__ void route_kernel(const int* __restrict__ idx32) {
    int s = blockIdx.x * blockDim.x + threadIdx.x;
    if (s < NSLOT) {
        int e = g_is64 ? idx32[2 * s] : idx32[s];
        e &= (NE - 1);
        int p = atomicAdd(&g_count[e], 1);
        g_slots[e][p] = s;
    }
}

// ---------------------------------------------------------------------------
// x: fp32 -> fp16 (tiny)
// ---------------------------------------------------------------------------
__global__ __launch_bounds__(256) void conv_f16_kernel(
    const float* __restrict__ src, __half* __restrict__ dst, int n8)
{
    int i = blockIdx.x * blockDim.x + threadIdx.x;
    if (i >= n8) return;
    float4 a = reinterpret_cast<const float4*>(src)[2 * i];
    float4 b = reinterpret_cast<const float4*>(src)[2 * i + 1];
    reinterpret_cast<uint4*>(dst)[i] = pack8h(a, b);
}

// ---------------------------------------------------------------------------
// GEMM1: h = silu(X @ w1[e]^T) * (X @ w3[e]^T). Pure fp16, fp32 acc. R11 EXACT.
// 3-stage pipeline, ONE barrier per chunk:
//   CP_WAIT -> __syncthreads -> cp.async(c+2) -> W LDG(c+1) -> MMA(c) -> W STS(c+1)
// Stage tiles: A, B1, B3 (each 128 x 32 fp16, 80B stride)
// ---------------------------------------------------------------------------
#define STAGE1B (3 * TB)                    // 30720
#define SMEM1_BYTES (1024 + 3 * STAGE1B)    // 93184

__global__ __launch_bounds__(512, 1) void gemm1_tc(
    const float* __restrict__ w1, const float* __restrict__ w3)
{
    const int e = blockIdx.z;
    const int ne = g_count[e];
    const int mBase = blockIdx.y * BM;
    if (mBase >= ne) return;
    const int nBase = blockIdx.x * BN;

    extern __shared__ char smem[];
    const uint32_t sb = smem_u32(smem);
    const int tid = threadIdx.x;
    const int wid = tid >> 5;
    const int lane = tid & 31;

    int* sSlot = reinterpret_cast<int*>(smem);
    if (tid < BM) {
        int m = mBase + tid;
        sSlot[tid] = (m < ne) ? g_slots[e][m] : -1;
    }
    __syncthreads();

    // --- A producer: one 16B granule per thread ---
    const int prow = tid >> 2;
    const int pcolg = tid & 3;
    const uint32_t adoff = 1024u + (uint32_t)prow * LDS_STRIDE + pcolg * 16;
    const __half* asrcp;
    {
        int s = sSlot[prow];
        int tok = (s >= 0 ? s : 0) >> 1;
        asrcp = g_x16 + (size_t)tok * ND + pcolg * 8;
    }

    // --- W producer: 16 fp32 -> 16 fp16 per thread per chunk (w1 or w3) ---
    const int wt    = tid >> 8;            // 0: w1, 1: w3
    const int wrow  = (tid & 255) >> 1;    // 0..127
    const int whalf = tid & 1;             // 16 floats each
    const float* wsrc = (wt == 0 ? w1 : w3)
        + (size_t)e * NI * ND + (size_t)(nBase + wrow) * ND + whalf * 16;
    const uint32_t wdoff = (uint32_t)wrow * LDS_STRIDE + whalf * 32;
    const uint32_t wtoff = (uint32_t)(1 + wt) * TB;   // B1 or B3 within stage

    // --- consumer: 16 warps = 4M x 4N, warp tile 32x32 ---
    const int warpM = wid & 3;
    const int warpN = wid >> 2;
    const uint32_t aoff = (uint32_t)(warpM * 32 + (lane & 15)) * LDS_STRIDE
                        + (uint32_t)(lane >> 4) * 16;
    const uint32_t boff = (uint32_t)(warpN * 32 + (lane & 7) + ((lane >> 3) & 2) * 4) * LDS_STRIDE
                        + (uint32_t)((lane >> 3) & 1) * 16;

    float acc1[2][4][4] = {};
    float acc3[2][4][4] = {};

    const int NCH = ND / BK;   // 32

    // --- prologue: cp A for chunks 0,1 (stages 0,1); convert+store W chunk 0 ---
    CP_ASYNC16(adoff + sb, asrcp);
    CP_COMMIT();
    CP_ASYNC16(adoff + sb + STAGE1B, asrcp + BK);
    CP_COMMIT();
    {
        float4 s0 = *reinterpret_cast<const float4*>(wsrc + 0);
        float4 s1 = *reinterpret_cast<const float4*>(wsrc + 4);
        float4 s2 = *reinterpret_cast<const float4*>(wsrc + 8);
        float4 s3 = *reinterpret_cast<const float4*>(wsrc + 12);
        *reinterpret_cast<uint4*>(smem + 1024u + wtoff + wdoff)      = pack8h(s0, s1);
        *reinterpret_cast<uint4*>(smem + 1024u + wtoff + wdoff + 16) = pack8h(s2, s3);
    }

    uint32_t stgRd = 0, stgW = STAGE1B, stgCp = 2 * STAGE1B;

    for (int c = 0; c < NCH; c++) {
        const bool haveCp = (c + 2 < NCH);
        const bool haveW  = (c + 1 < NCH);

        if (c + 1 < NCH) { CP_WAIT(1); } else { CP_WAIT(0); }
        __syncthreads();
        if (haveCp) {
            const int kt2 = (c + 2) * BK;
            CP_ASYNC16(adoff + sb + stgCp, asrcp + kt2);
            CP_COMMIT();
        }
        float4 s0, s1, s2, s3;
        if (haveW) {
            const int kt = (c + 1) * BK;
            s0 = *reinterpret_cast<const float4*>(wsrc + kt + 0);
            s1 = *reinterpret_cast<const float4*>(wsrc + kt + 4);
            s2 = *reinterpret_cast<const float4*>(wsrc + kt + 8);
            s3 = *reinterpret_cast<const float4*>(wsrc + kt + 12);
        }

        const uint32_t bb = sb + 1024u + stgRd;
        const uint32_t tA = bb;
        const uint32_t tB1 = bb + TB, tB3 = bb + 2 * TB;

        #pragma unroll
        for (int kb = 0; kb < 2; kb++) {
            const uint32_t ko = kb * 32;
            uint32_t a[2][4];
            #pragma unroll
            for (int mb = 0; mb < 2; mb++)
                LDSM4(a[mb], tA + aoff + mb * (16 * LDS_STRIDE) + ko);
            #pragma unroll
            for (int nb2 = 0; nb2 < 2; nb2++) {
                const uint32_t no = nb2 * (16 * LDS_STRIDE);
                const int j0 = 2 * nb2, j1 = 2 * nb2 + 1;
                uint32_t b1[4], b3[4];
                LDSM4(b1, tB1 + boff + no + ko);
                LDSM4(b3, tB3 + boff + no + ko);
                MMA_F16(acc1[0][j0], a[0], b1[0], b1[1]);
                MMA_F16(acc1[0][j1], a[0], b1[2], b1[3]);
                MMA_F16(acc1[1][j0], a[1], b1[0], b1[1]);
                MMA_F16(acc1[1][j1], a[1], b1[2], b1[3]);
                MMA_F16(acc3[0][j0], a[0], b3[0], b3[1]);
                MMA_F16(acc3[0][j1], a[0], b3[2], b3[3]);
                MMA_F16(acc3[1][j0], a[1], b3[0], b3[1]);
                MMA_F16(acc3[1][j1], a[1], b3[2], b3[3]);
            }
        }

        if (haveW) {
            *reinterpret_cast<uint4*>(smem + 1024u + stgW + wtoff + wdoff)      = pack8h(s0, s1);
            *reinterpret_cast<uint4*>(smem + 1024u + stgW + wtoff + wdoff + 16) = pack8h(s2, s3);
        }
        const uint32_t t = stgRd;
        stgRd = stgW; stgW = stgCp; stgCp = t;
    }

    // --- epilogue: SwiGLU, store h as fp16 ---
    const int g = lane >> 2;
    const int tg = lane & 3;
    #pragma unroll
    for (int mb = 0; mb < 2; mb++) {
        #pragma unroll
        for (int half = 0; half < 2; half++) {
            const int r = warpM * 32 + mb * 16 + g + half * 8;
            const int s = sSlot[r];
            if (s < 0) continue;
            #pragma unroll
            for (int nb = 0; nb < 4; nb++) {
                const float v1a = acc1[mb][nb][half * 2];
                const float v1b = acc1[mb][nb][half * 2 + 1];
                const float v3a = acc3[mb][nb][half * 2];
                const float v3b = acc3[mb][nb][half * 2 + 1];
                const float ha = v1a / (1.0f + __expf(-v1a)) * v3a;
                const float hb = v1b / (1.0f + __expf(-v1b)) * v3b;
                const size_t o = (size_t)s * NI + (nBase + warpN * 32 + nb * 8 + tg * 2);
                *reinterpret_cast<uint32_t*>(g_h16 + o) = pack2h(ha, hb);
            }
        }
    }
}

// ---------------------------------------------------------------------------
// GEMM2: out[slot,:] = h[slot,:] @ w2[e]^T. Pure fp16.
// Block 128(M) x 256(N), 512 threads (16 warps = 4M x 4N, warp tile 32x64).
// Same 3-stage / 1-barrier scheme; per kb the R11 inner pattern runs twice
// (nb2 pairs (0,1) and (2,3)). Effective grid ~80 CTAs -> single wave.
// Stage tiles: A (128 rows), B (256 rows).
// ---------------------------------------------------------------------------
#define STAGE2B (TB + TB2)                  // 30720
#define SMEM2_BYTES (1024 + 3 * STAGE2B)    // 93184

__global__ __launch_bounds__(512, 1) void gemm2_tc(
    const float* __restrict__ w2, float* __restrict__ out)
{
    const int e = blockIdx.z;
    const int ne = g_count[e];
    const int mBase = blockIdx.y * BM;
    if (mBase >= ne) return;
    const int nBase = blockIdx.x * BN2;

    extern __shared__ char smem[];
    const uint32_t sb = smem_u32(smem);
    const int tid = threadIdx.x;
    const int wid = tid >> 5;
    const int lane = tid & 31;

    int* sSlot = reinterpret_cast<int*>(smem);
    if (tid < BM) {
        int m = mBase + tid;
        sSlot[tid] = (m < ne) ? g_slots[e][m] : -1;
    }
    __syncthreads();

    // --- A producer: one 16B granule per thread (128 rows x 4) ---
    const int prow = tid >> 2;
    const int pcolg = tid & 3;
    const uint32_t adoff = 1024u + (uint32_t)prow * LDS_STRIDE + pcolg * 16;
    const __half* asrcp;
    {
        int s = sSlot[prow];
        int sl = (s >= 0 ? s : 0);
        asrcp = g_h16 + (size_t)sl * NI + pcolg * 8;
    }

    // --- W producer: 16 fp32 -> 16 fp16 per thread per chunk (256 rows x 2) ---
    const int wrow  = tid >> 1;            // 0..255
    const int whalf = tid & 1;             // 16 floats each
    const float* wsrc = w2 + (size_t)e * ND * NI + (size_t)(nBase + wrow) * NI + whalf * 16;
    const uint32_t wdoff = (uint32_t)wrow * LDS_STRIDE + whalf * 32;
    const uint32_t wtoff = TB;             // B tile after the 128-row A tile

    // --- consumer: 16 warps = 4M x 4N, warp tile 32x64 ---
    const int warpM = wid & 3;
    const int warpN = wid >> 2;
    const uint32_t aoff = (uint32_t)(warpM * 32 + (lane & 15)) * LDS_STRIDE
                        + (uint32_t)(lane >> 4) * 16;
    const uint32_t boff = (uint32_t)(warpN * 64 + (lane & 7) + ((lane >> 3) & 2) * 4) * LDS_STRIDE
                        + (uint32_t)((lane >> 3) & 1) * 16;

    float acc[2][8][4] = {};

    const int NCH = NI / BK;   // 88

    // --- prologue ---
    CP_ASYNC16(adoff + sb, asrcp);
    CP_COMMIT();
    CP_ASYNC16(adoff + sb + STAGE2B, asrcp + BK);
    CP_COMMIT();
    {
        float4 s0 = *reinterpret_cast<const float4*>(wsrc + 0);
        float4 s1 = *reinterpret_cast<const float4*>(wsrc + 4);
        float4 s2 = *reinterpret_cast<const float4*>(wsrc + 8);
        float4 s3 = *reinterpret_cast<const float4*>(wsrc + 12);
        *reinterpret_cast<uint4*>(smem + 1024u + wtoff + wdoff)      = pack8h(s0, s1);
        *reinterpret_cast<uint4*>(smem + 1024u + wtoff + wdoff + 16) = pack8h(s2, s3);
    }

    uint32_t stgRd = 0, stgW = STAGE2B, stgCp = 2 * STAGE2B;

    for (int c = 0; c < NCH; c++) {
        const bool haveCp = (c + 2 < NCH);
        const bool haveW  = (c + 1 < NCH);

        if (c + 1 < NCH) { CP_WAIT(1); } else { CP_WAIT(0); }
        __syncthreads();
        if (haveCp) {
            const int kt2 = (c + 2) * BK;
            CP_ASYNC16(adoff + sb + stgCp, asrcp + kt2);
            CP_COMMIT();
        }
        float4 s0, s1, s2, s3;
        if (haveW) {
            const int kt = (c + 1) * BK;
            s0 = *reinterpret_cast<const float4*>(wsrc + kt + 0);
            s1 = *reinterpret_cast<const float4*>(wsrc + kt + 4);
            s2 = *reinterpret_cast<const float4*>(wsrc + kt + 8);
            s3 = *reinterpret_cast<const float4*>(wsrc + kt + 12);
        }

        const uint32_t bb = sb + 1024u + stgRd;
        const uint32_t tA = bb;
        const uint32_t tBh = bb + TB;

        #pragma unroll
        for (int kb = 0; kb < 2; kb++) {
            const uint32_t ko = kb * 32;
            uint32_t a[2][4];
            #pragma unroll
            for (int mb = 0; mb < 2; mb++)
                LDSM4(a[mb], tA + aoff + mb * (16 * LDS_STRIDE) + ko);
            #pragma unroll
            for (int p = 0; p < 2; p++) {      // nb2 pairs (0,1) and (2,3)
                const int j0 = 4 * p, j1 = 4 * p + 1, j2 = 4 * p + 2, j3 = 4 * p + 3;
                uint32_t bh0[4], bh1[4];
                LDSM4(bh0, tBh + boff + (2 * p)     * (16 * LDS_STRIDE) + ko);
                LDSM4(bh1, tBh + boff + (2 * p + 1) * (16 * LDS_STRIDE) + ko);
                // 8 distinct C targets per pair (R11 gemm2 pattern)
                MMA_F16(acc[0][j0], a[0], bh0[0], bh0[1]);
                MMA_F16(acc[0][j1], a[0], bh0[2], bh0[3]);
                MMA_F16(acc[1][j0], a[1], bh0[0], bh0[1]);
                MMA_F16(acc[1][j1], a[1], bh0[2], bh0[3]);
                MMA_F16(acc[0][j2], a[0], bh1[0], bh1[1]);
                MMA_F16(acc[0][j3], a[0], bh1[2], bh1[3]);
                MMA_F16(acc[1][j2], a[1], bh1[0], bh1[1]);
                MMA_F16(acc[1][j3], a[1], bh1[2], bh1[3]);
            }
        }

        if (haveW) {
            *reinterpret_cast<uint4*>(smem + 1024u + stgW + wtoff + wdoff)      = pack8h(s0, s1);
            *reinterpret_cast<uint4*>(smem + 1024u + stgW + wtoff + wdoff + 16) = pack8h(s2, s3);
        }
        const uint32_t t = stgRd;
        stgRd = stgW; stgW = stgCp; stgCp = t;
    }

    // --- epilogue: fp32 direct stores ---
    const int g = lane >> 2;
    const int tg = lane & 3;
    #pragma unroll
    for (int mb = 0; mb < 2; mb++) {
        #pragma unroll
        for (int half = 0; half < 2; half++) {
            const int r = warpM * 32 + mb * 16 + g + half * 8;
            const int s = sSlot[r];
            if (s < 0) continue;
            #pragma unroll
            for (int nb = 0; nb < 8; nb++) {
                float2 v;
                v.x = acc[mb][nb][half * 2];
                v.y = acc[mb][nb][half * 2 + 1];
                const size_t o = (size_t)s * ND + (nBase + warpN * 64 + nb * 8 + tg * 2);
                *reinterpret_cast<float2*>(out + o) = v;
            }
        }
    }
}

// ---------------------------------------------------------------------------
// Launch. Inputs (metadata order): x, w1, w2, w3, expert_indices.
// ---------------------------------------------------------------------------
extern "C" void kernel_launch(void* const* d_in, const int* in_sizes, int n_in,
                              void* d_out, int out_size) {
    const float* x  = (const float*)d_in[0];
    const float* w1 = (const float*)d_in[1];
    const float* w2 = (const float*)d_in[2];
    const float* w3 = (const float*)d_in[3];
    const int*   idx = (const int*)d_in[4];
    float* out = (float*)d_out;

    cudaFuncSetAttribute(gemm1_tc, cudaFuncAttributeMaxDynamicSharedMemorySize, SMEM1_BYTES);
    cudaFuncSetAttribute(gemm2_tc, cudaFuncAttributeMaxDynamicSharedMemorySize, SMEM2_BYTES);

    __half* x16;
    cudaGetSymbolAddress((void**)&x16, g_x16);

    detect_and_zero_kernel<<<1, 256>>>(idx);
    route_kernel<<<NSLOT / 256, 256>>>(idx);

    const int nX8 = NT * ND / 8;
    conv_f16_kernel<<<nX8 / 256, 256>>>(x, x16, nX8);

    gemm1_tc<<<dim3(NI / BN, NSLOT / BM, NE), 512, SMEM1_BYTES>>>(w1, w3);
    gemm2_tc<<<dim3(ND / BN2, NSLOT / BM, NE), 512, SMEM2_BYTES>>>(w2, out);
}

// round 17
// speedup vs baseline: 1.1475x; 1.1120x over previous
#include <cuda_runtime.h>
#include <cuda_fp16.h>
#include <cstdint>
#include <math.h>

// Problem constants
#define NT 1024
#define NA 2
#define NE 8
#define NI 2816
#define ND 1024
#define NSLOT (NT * NA)

// GEMM tiling: block 128x128x32, 512 threads (16 warps: 4M x 4N), 3-stage pipe
#define BM 128
#define BN 128
#define BK 32
#define LDS_STRIDE 80              // bytes per smem tile row (32*2 padded to 80)
#define TB (128 * LDS_STRIDE)      // one tile: 128 rows x 80B = 10240 B

// ---------------------------------------------------------------------------
// Device global scratch
// ---------------------------------------------------------------------------
__device__ int g_count[NE];
__device__ int g_slots[NE][NSLOT];
__device__ int g_is64;

__device__ __align__(16) __half g_x16[NT * ND];
__device__ __align__(16) __half g_h16[(size_t)NSLOT * NI];

// ---------------------------------------------------------------------------
// PTX helpers (base-target sm_103 features only)
// ---------------------------------------------------------------------------
__device__ __forceinline__ uint32_t smem_u32(const void* p) {
    uint32_t a;
    asm("{ .reg .u64 t; cvta.to.shared.u64 t, %1; cvt.u32.u64 %0, t; }"
        : "=r"(a) : "l"(p));
    return a;
}

#define LDSM4(R, addr) \
    asm volatile("ldmatrix.sync.aligned.m8n8.x4.shared.b16 {%0,%1,%2,%3}, [%4];" \
        : "=r"((R)[0]), "=r"((R)[1]), "=r"((R)[2]), "=r"((R)[3]) : "r"(addr))

#define MMA_F16(C, A, B0, B1) \
    asm volatile("mma.sync.aligned.m16n8k16.row.col.f32.f16.f16.f32 " \
        "{%0,%1,%2,%3}, {%4,%5,%6,%7}, {%8,%9}, {%0,%1,%2,%3};" \
        : "+f"((C)[0]), "+f"((C)[1]), "+f"((C)[2]), "+f"((C)[3]) \
        : "r"((A)[0]), "r"((A)[1]), "r"((A)[2]), "r"((A)[3]), "r"(B0), "r"(B1))

#define CP_ASYNC16(dst, src) \
    asm volatile("cp.async.cg.shared.global [%0], [%1], 16;" :: "r"(dst), "l"(src))
#define CP_COMMIT() asm volatile("cp.async.commit_group;" ::: "memory")
#define CP_WAIT(N) asm volatile("cp.async.wait_group %0;" :: "n"(N) : "memory")

__device__ __forceinline__ uint32_t pack2h(float a, float b) {
    __half2 h = __floats2half2_rn(a, b);
    return *reinterpret_cast<uint32_t*>(&h);
}
// 8 fp32 -> 8 packed fp16 (uint4)
__device__ __forceinline__ uint4 pack8h(const float4& a, const float4& b) {
    uint4 r;
    r.x = pack2h(a.x, a.y);
    r.y = pack2h(a.z, a.w);
    r.z = pack2h(b.x, b.y);
    r.w = pack2h(b.z, b.w);
    return r;
}

// ---------------------------------------------------------------------------
// Routing
// ---------------------------------------------------------------------------
__global__ void detect_and_zero_kernel(const int* __restrict__ idx32) {
    __shared__ int any;
    if (threadIdx.x == 0) any = 0;
    if (threadIdx.x < NE) g_count[threadIdx.x] = 0;
    __syncthreads();
    int local = 0;
    for (int i = threadIdx.x; i < NSLOT / 2; i += blockDim.x)
        local |= idx32[2 * i + 1];
    if (local) atomicOr(&any, 1);
    __syncthreads();
    if (threadIdx.x == 0) g_is64 = (any == 0) ? 1 : 0;
}

__global__ void route_kernel(const int* __restrict__ idx32) {
    int s = blockIdx.x * blockDim.x + threadIdx.x;
    if (s < NSLOT) {
        int e = g_is64 ? idx32[2 * s] : idx32[s];
        e &= (NE - 1);
        int p = atomicAdd(&g_count[e], 1);
        g_slots[e][p] = s;
    }
}

// ---------------------------------------------------------------------------
// x: fp32 -> fp16 (tiny)
// ---------------------------------------------------------------------------
__global__ __launch_bounds__(256) void conv_f16_kernel(
    const float* __restrict__ src, __half* __restrict__ dst, int n8)
{
    int i = blockIdx.x * blockDim.x + threadIdx.x;
    if (i >= n8) return;
    float4 a = reinterpret_cast<const float4*>(src)[2 * i];
    float4 b = reinterpret_cast<const float4*>(src)[2 * i + 1];
    reinterpret_cast<uint4*>(dst)[i] = pack8h(a, b);
}

// ---------------------------------------------------------------------------
// GEMM1: h = silu(X @ w1[e]^T) * (X @ w3[e]^T). Pure fp16 operands, fp32 acc.
// 3-stage pipeline, ONE barrier per chunk (R7 skeleton):
//   CP_WAIT -> __syncthreads -> cp.async(c+2) -> W LDG(c+1) -> MMA(c) -> W STS(c+1)
// Stage tiles: A, B1, B3 (each 128 x 32 fp16, 80B stride)
// ---------------------------------------------------------------------------
#define STAGE1B (3 * TB)                    // 30720
#define SMEM1_BYTES (1024 + 3 * STAGE1B)    // 93184

__global__ __launch_bounds__(512, 1) void gemm1_tc(
    const float* __restrict__ w1, const float* __restrict__ w3)
{
    const int e = blockIdx.z;
    const int ne = g_count[e];
    const int mBase = blockIdx.y * BM;
    if (mBase >= ne) return;
    const int nBase = blockIdx.x * BN;

    extern __shared__ char smem[];
    const uint32_t sb = smem_u32(smem);
    const int tid = threadIdx.x;
    const int wid = tid >> 5;
    const int lane = tid & 31;

    int* sSlot = reinterpret_cast<int*>(smem);
    if (tid < BM) {
        int m = mBase + tid;
        sSlot[tid] = (m < ne) ? g_slots[e][m] : -1;
    }
    __syncthreads();

    // --- A producer: one 16B granule per thread (512 granules = full tile) ---
    const int prow = tid >> 2;
    const int pcolg = tid & 3;
    const uint32_t adoff = 1024u + (uint32_t)prow * LDS_STRIDE + pcolg * 16;
    const __half* asrcp;
    {
        int s = sSlot[prow];
        int tok = (s >= 0 ? s : 0) >> 1;
        asrcp = g_x16 + (size_t)tok * ND + pcolg * 8;
    }

    // --- W producer: 16 fp32 -> 16 fp16 per thread per chunk (w1 or w3) ---
    const int wt    = tid >> 8;            // 0: w1, 1: w3
    const int wrow  = (tid & 255) >> 1;    // 0..127
    const int whalf = tid & 1;             // 16 floats each
    const float* wsrc = (wt == 0 ? w1 : w3)
        + (size_t)e * NI * ND + (size_t)(nBase + wrow) * ND + whalf * 16;
    const uint32_t wdoff = (uint32_t)wrow * LDS_STRIDE + whalf * 32;
    const uint32_t wtoff = (uint32_t)(1 + wt) * TB;   // B1 or B3 within stage

    // --- consumer: 16 warps = 4M x 4N, warp tile 32x32 ---
    const int warpM = wid & 3;
    const int warpN = wid >> 2;
    const uint32_t aoff = (uint32_t)(warpM * 32 + (lane & 15)) * LDS_STRIDE
                        + (uint32_t)(lane >> 4) * 16;
    const uint32_t boff = (uint32_t)(warpN * 32 + (lane & 7) + ((lane >> 3) & 2) * 4) * LDS_STRIDE
                        + (uint32_t)((lane >> 3) & 1) * 16;

    float acc1[2][4][4] = {};
    float acc3[2][4][4] = {};

    const int NCH = ND / BK;   // 32

    // --- prologue: cp A for chunks 0,1 (stages 0,1); convert+store W chunk 0 ---
    CP_ASYNC16(adoff + sb, asrcp);
    CP_COMMIT();
    CP_ASYNC16(adoff + sb + STAGE1B, asrcp + BK);
    CP_COMMIT();
    {
        float4 s0 = *reinterpret_cast<const float4*>(wsrc + 0);
        float4 s1 = *reinterpret_cast<const float4*>(wsrc + 4);
        float4 s2 = *reinterpret_cast<const float4*>(wsrc + 8);
        float4 s3 = *reinterpret_cast<const float4*>(wsrc + 12);
        *reinterpret_cast<uint4*>(smem + 1024u + wtoff + wdoff)      = pack8h(s0, s1);
        *reinterpret_cast<uint4*>(smem + 1024u + wtoff + wdoff + 16) = pack8h(s2, s3);
    }

    uint32_t stgRd = 0, stgW = STAGE1B, stgCp = 2 * STAGE1B;

    for (int c = 0; c < NCH; c++) {
        const bool haveCp = (c + 2 < NCH);
        const bool haveW  = (c + 1 < NCH);

        if (c + 1 < NCH) { CP_WAIT(1); } else { CP_WAIT(0); }
        __syncthreads();
        if (haveCp) {
            const int kt = (c + 2) * BK;
            CP_ASYNC16(adoff + sb + stgCp, asrcp + kt);
            CP_COMMIT();
        }
        float4 s0, s1, s2, s3;
        if (haveW) {
            const int kt = (c + 1) * BK;
            s0 = *reinterpret_cast<const float4*>(wsrc + kt + 0);
            s1 = *reinterpret_cast<const float4*>(wsrc + kt + 4);
            s2 = *reinterpret_cast<const float4*>(wsrc + kt + 8);
            s3 = *reinterpret_cast<const float4*>(wsrc + kt + 12);
        }

        const uint32_t bb = sb + 1024u + stgRd;
        const uint32_t tA = bb;
        const uint32_t tB1 = bb + TB, tB3 = bb + 2 * TB;

        #pragma unroll
        for (int kb = 0; kb < 2; kb++) {
            const uint32_t ko = kb * 32;
            uint32_t a[2][4];
            #pragma unroll
            for (int mb = 0; mb < 2; mb++)
                LDSM4(a[mb], tA + aoff + mb * (16 * LDS_STRIDE) + ko);
            #pragma unroll
            for (int nb2 = 0; nb2 < 2; nb2++) {
                const uint32_t no = nb2 * (16 * LDS_STRIDE);
                const int j0 = 2 * nb2, j1 = 2 * nb2 + 1;
                uint32_t b1[4], b3[4];
                LDSM4(b1, tB1 + boff + no + ko);
                LDSM4(b3, tB3 + boff + no + ko);
                // 8 distinct C targets
                MMA_F16(acc1[0][j0], a[0], b1[0], b1[1]);
                MMA_F16(acc1[0][j1], a[0], b1[2], b1[3]);
                MMA_F16(acc1[1][j0], a[1], b1[0], b1[1]);
                MMA_F16(acc1[1][j1], a[1], b1[2], b1[3]);
                MMA_F16(acc3[0][j0], a[0], b3[0], b3[1]);
                MMA_F16(acc3[0][j1], a[0], b3[2], b3[3]);
                MMA_F16(acc3[1][j0], a[1], b3[0], b3[1]);
                MMA_F16(acc3[1][j1], a[1], b3[2], b3[3]);
            }
        }

        if (haveW) {
            *reinterpret_cast<uint4*>(smem + 1024u + stgW + wtoff + wdoff)      = pack8h(s0, s1);
            *reinterpret_cast<uint4*>(smem + 1024u + stgW + wtoff + wdoff + 16) = pack8h(s2, s3);
        }
        const uint32_t t = stgRd;
        stgRd = stgW; stgW = stgCp; stgCp = t;
    }

    // --- epilogue: SwiGLU, store h as fp16 ---
    const int g = lane >> 2;
    const int tg = lane & 3;
    #pragma unroll
    for (int mb = 0; mb < 2; mb++) {
        #pragma unroll
        for (int half = 0; half < 2; half++) {
            const int r = warpM * 32 + mb * 16 + g + half * 8;
            const int s = sSlot[r];
            if (s < 0) continue;
            #pragma unroll
            for (int nb = 0; nb < 4; nb++) {
                const float v1a = acc1[mb][nb][half * 2];
                const float v1b = acc1[mb][nb][half * 2 + 1];
                const float v3a = acc3[mb][nb][half * 2];
                const float v3b = acc3[mb][nb][half * 2 + 1];
                const float ha = v1a / (1.0f + __expf(-v1a)) * v3a;
                const float hb = v1b / (1.0f + __expf(-v1b)) * v3b;
                const size_t o = (size_t)s * NI + (nBase + warpN * 32 + nb * 8 + tg * 2);
                *reinterpret_cast<uint32_t*>(g_h16 + o) = pack2h(ha, hb);
            }
        }
    }
}

// ---------------------------------------------------------------------------
// GEMM2: out[slot,:] = h[slot,:] @ w2[e]^T. Pure fp16.
// Same 3-stage / 1-barrier scheme. Stage tiles: A, B.
// ---------------------------------------------------------------------------
#define STAGE2B (2 * TB)                    // 20480
#define SMEM2_BYTES (1024 + 3 * STAGE2B)    // 62464

__global__ __launch_bounds__(512, 1) void gemm2_tc(
    const float* __restrict__ w2, float* __restrict__ out)
{
    const int e = blockIdx.z;
    const int ne = g_count[e];
    const int mBase = blockIdx.y * BM;
    if (mBase >= ne) return;
    const int nBase = blockIdx.x * BN;

    extern __shared__ char smem[];
    const uint32_t sb = smem_u32(smem);
    const int tid = threadIdx.x;
    const int wid = tid >> 5;
    const int lane = tid & 31;

    int* sSlot = reinterpret_cast<int*>(smem);
    if (tid < BM) {
        int m = mBase + tid;
        sSlot[tid] = (m < ne) ? g_slots[e][m] : -1;
    }
    __syncthreads();

    const int prow = tid >> 2;
    const int pcolg = tid & 3;
    const uint32_t adoff = 1024u + (uint32_t)prow * LDS_STRIDE + pcolg * 16;
    const __half* asrcp;
    {
        int s = sSlot[prow];
        int sl = (s >= 0 ? s : 0);
        asrcp = g_h16 + (size_t)sl * NI + pcolg * 8;
    }

    // W producer: 8 fp32 -> 8 fp16 per thread per chunk
    const int wrow = tid >> 2;
    const int wq   = tid & 3;
    const float* wsrc = w2 + (size_t)e * ND * NI + (size_t)(nBase + wrow) * NI + wq * 8;
    const uint32_t wdoff = (uint32_t)wrow * LDS_STRIDE + wq * 16;
    const uint32_t wtoff = TB;

    const int warpM = wid & 3;
    const int warpN = wid >> 2;
    const uint32_t aoff = (uint32_t)(warpM * 32 + (lane & 15)) * LDS_STRIDE
                        + (uint32_t)(lane >> 4) * 16;
    const uint32_t boff = (uint32_t)(warpN * 32 + (lane & 7) + ((lane >> 3) & 2) * 4) * LDS_STRIDE
                        + (uint32_t)((lane >> 3) & 1) * 16;

    float acc[2][4][4] = {};

    const int NCH = NI / BK;   // 88

    // --- prologue ---
    CP_ASYNC16(adoff + sb, asrcp);
    CP_COMMIT();
    CP_ASYNC16(adoff + sb + STAGE2B, asrcp + BK);
    CP_COMMIT();
    {
        float4 s0 = *reinterpret_cast<const float4*>(wsrc + 0);
        float4 s1 = *reinterpret_cast<const float4*>(wsrc + 4);
        *reinterpret_cast<uint4*>(smem + 1024u + wtoff + wdoff) = pack8h(s0, s1);
    }

    uint32_t stgRd = 0, stgW = STAGE2B, stgCp = 2 * STAGE2B;

    for (int c = 0; c < NCH; c++) {
        const bool haveCp = (c + 2 < NCH);
        const bool haveW  = (c + 1 < NCH);

        if (c + 1 < NCH) { CP_WAIT(1); } else { CP_WAIT(0); }
        __syncthreads();
        if (haveCp) {
            const int kt = (c + 2) * BK;
            CP_ASYNC16(adoff + sb + stgCp, asrcp + kt);
            CP_COMMIT();
        }
        float4 s0, s1;
        if (haveW) {
            const int kt = (c + 1) * BK;
            s0 = *reinterpret_cast<const float4*>(wsrc + kt + 0);
            s1 = *reinterpret_cast<const float4*>(wsrc + kt + 4);
        }

        const uint32_t bb = sb + 1024u + stgRd;
        const uint32_t tA = bb;
        const uint32_t tBh = bb + TB;

        #pragma unroll
        for (int kb = 0; kb < 2; kb++) {
            const uint32_t ko = kb * 32;
            uint32_t a[2][4];
            #pragma unroll
            for (int mb = 0; mb < 2; mb++)
                LDSM4(a[mb], tA + aoff + mb * (16 * LDS_STRIDE) + ko);
            uint32_t bh0[4], bh1[4];
            LDSM4(bh0, tBh + boff + ko);
            LDSM4(bh1, tBh + boff + 16 * LDS_STRIDE + ko);
            MMA_F16(acc[0][0], a[0], bh0[0], bh0[1]);
            MMA_F16(acc[0][1], a[0], bh0[2], bh0[3]);
            MMA_F16(acc[1][0], a[1], bh0[0], bh0[1]);
            MMA_F16(acc[1][1], a[1], bh0[2], bh0[3]);
            MMA_F16(acc[0][2], a[0], bh1[0], bh1[1]);
            MMA_F16(acc[0][3], a[0], bh1[2], bh1[3]);
            MMA_F16(acc[1][2], a[1], bh1[0], bh1[1]);
            MMA_F16(acc[1][3], a[1], bh1[2], bh1[3]);
        }

        if (haveW) {
            *reinterpret_cast<uint4*>(smem + 1024u + stgW + wtoff + wdoff) = pack8h(s0, s1);
        }
        const uint32_t t = stgRd;
        stgRd = stgW; stgW = stgCp; stgCp = t;
    }

    // --- epilogue: fp32 direct stores ---
    const int g = lane >> 2;
    const int tg = lane & 3;
    #pragma unroll
    for (int mb = 0; mb < 2; mb++) {
        #pragma unroll
        for (int half = 0; half < 2; half++) {
            const int r = warpM * 32 + mb * 16 + g + half * 8;
            const int s = sSlot[r];
            if (s < 0) continue;
            #pragma unroll
            for (int nb = 0; nb < 4; nb++) {
                float2 v;
                v.x = acc[mb][nb][half * 2];
                v.y = acc[mb][nb][half * 2 + 1];
                const size_t o = (size_t)s * ND + (nBase + warpN * 32 + nb * 8 + tg * 2);
                *reinterpret_cast<float2*>(out + o) = v;
            }
        }
    }
}

// ---------------------------------------------------------------------------
// Launch. Inputs (metadata order): x, w1, w2, w3, expert_indices.
// ---------------------------------------------------------------------------
extern "C" void kernel_launch(void* const* d_in, const int* in_sizes, int n_in,
                              void* d_out, int out_size) {
    const float* x  = (const float*)d_in[0];
    const float* w1 = (const float*)d_in[1];
    const float* w2 = (const float*)d_in[2];
    const float* w3 = (const float*)d_in[3];
    const int*   idx = (const int*)d_in[4];
    float* out = (float*)d_out;

    cudaFuncSetAttribute(gemm1_tc, cudaFuncAttributeMaxDynamicSharedMemorySize, SMEM1_BYTES);
    cudaFuncSetAttribute(gemm2_tc, cudaFuncAttributeMaxDynamicSharedMemorySize, SMEM2_BYTES);

    __half* x16;
    cudaGetSymbolAddress((void**)&x16, g_x16);

    detect_and_zero_kernel<<<1, 256>>>(idx);
    route_kernel<<<NSLOT / 256, 256>>>(idx);

    const int nX8 = NT * ND / 8;
    conv_f16_kernel<<<nX8 / 256, 256>>>(x, x16, nX8);

    gemm1_tc<<<dim3(NI / BN, NSLOT / BM, NE), 512, SMEM1_BYTES>>>(w1, w3);
    gemm2_tc<<<dim3(ND / BN, NSLOT / BM, NE), 512, SMEM2_BYTES>>>(w2, out);
}